// round 6
// baseline (speedup 1.0000x reference)
#include <cuda_runtime.h>

#define NN 100000
#define NE 1250000
#define D  64
#define NB 16
#define NBLK_SCAN 391   // ceil(100000/256)

// Scratch (no allocs). Invariant: g_cnt is ZERO at entry of every launch
// (zero at module load; k_scan3 re-zeroes it each launch).
__device__ float g_h[(size_t)NN * D];   // aggregated sum of x[src] per dst
__device__ float g_deg[NN];             // in-degree (float)
__device__ int   g_cnt[NN];             // histogram (self-cleaning)
__device__ int   g_off[NN + 1];         // exclusive offsets
__device__ int   g_pos[NN];             // running fill positions
__device__ int   g_blk[512];            // block sums for scan
__device__ int   g_srcs[NE];            // src ids sorted by dst
__device__ float g_Wm[D * D];
__device__ float g_Ws[D * D];
__device__ float g_bm[D];
__device__ float g_bs[D];

// ---------------------------------------------------------------------------
// 1) Histogram of dst (+ weight reconstruction hidden in block 0)
// ---------------------------------------------------------------------------
__global__ void k_hist(const int* __restrict__ ei,
                       const float* __restrict__ bmw, const float* __restrict__ bmb,
                       const float* __restrict__ bsw, const float* __restrict__ bsb,
                       const float* __restrict__ lc) {
    if (blockIdx.x == 0) {
        __shared__ float c[NB];
        if (threadIdx.x < NB) c[threadIdx.x] = lc[threadIdx.x];
        __syncthreads();
        for (int idx = threadIdx.x; idx < D * D; idx += 256) {
            float wm = 0.f, ws = 0.f;
            #pragma unroll
            for (int b = 0; b < NB; b++) {
                wm = fmaf(bmw[idx * NB + b], c[b], wm);
                ws = fmaf(bsw[idx * NB + b], c[b], ws);
            }
            g_Wm[idx] = wm;
            g_Ws[idx] = ws;
        }
        if (threadIdx.x < D) {
            int o = threadIdx.x;
            float bm = 0.f, bs = 0.f;
            #pragma unroll
            for (int b = 0; b < NB; b++) {
                bm = fmaf(bmb[o * NB + b], c[b], bm);
                bs = fmaf(bsb[o * NB + b], c[b], bs);
            }
            g_bm[o] = bm;
            g_bs[o] = bs;
        }
        return;
    }
    unsigned e = (blockIdx.x - 1) * 256u + threadIdx.x;
    if (e < NE) atomicAdd(&g_cnt[__ldg(ei + NE + e)], 1);
}

// ---------------------------------------------------------------------------
// 2..4) Exclusive scan of g_cnt -> g_off (three tiny kernels)
// ---------------------------------------------------------------------------
__global__ void k_scan1() {
    __shared__ int s[256];
    int t = threadIdx.x;
    int i = blockIdx.x * 256 + t;
    int v = (i < NN) ? g_cnt[i] : 0;
    s[t] = v;
    __syncthreads();
    #pragma unroll
    for (int d = 1; d < 256; d <<= 1) {
        int u = (t >= d) ? s[t - d] : 0;
        __syncthreads();
        s[t] += u;
        __syncthreads();
    }
    if (i < NN) g_off[i] = s[t] - v;          // exclusive within block
    if (t == 255) g_blk[blockIdx.x] = s[255]; // block total
}

__global__ void k_scan2() {
    __shared__ int s[512];
    int t = threadIdx.x;
    int v = (t < NBLK_SCAN) ? g_blk[t] : 0;
    s[t] = v;
    __syncthreads();
    #pragma unroll
    for (int d = 1; d < 512; d <<= 1) {
        int u = (t >= d) ? s[t - d] : 0;
        __syncthreads();
        s[t] += u;
        __syncthreads();
    }
    if (t < NBLK_SCAN) g_blk[t] = s[t] - v;   // exclusive block offsets
}

__global__ void k_scan3() {
    int i = blockIdx.x * 256 + threadIdx.x;
    if (i < NN) {
        int o = g_off[i] + g_blk[blockIdx.x];
        g_off[i] = o;
        g_pos[i] = o;
        g_cnt[i] = 0;                         // self-clean for next launch
    }
    if (i == 0) g_off[NN] = NE;
}

// ---------------------------------------------------------------------------
// 5) Fill sorted src list (counting-sort scatter pass)
// ---------------------------------------------------------------------------
__global__ void k_fill(const int* __restrict__ ei) {
    unsigned e = blockIdx.x * 256u + threadIdx.x;
    if (e >= NE) return;
    int d = __ldg(ei + NE + e);
    int p = atomicAdd(&g_pos[d], 1);
    g_srcs[p] = __ldg(ei + e);
}

// ---------------------------------------------------------------------------
// 6) Atomic-free aggregation: one warp per dst node, row in registers
// ---------------------------------------------------------------------------
__global__ void __launch_bounds__(256)
k_agg(const float2* __restrict__ x2) {
    int wid = (blockIdx.x * 256 + threadIdx.x) >> 5;
    if (wid >= NN) return;
    int l = threadIdx.x & 31;
    int start = __ldg(&g_off[wid]);
    int end   = __ldg(&g_off[wid + 1]);

    float2 acc = make_float2(0.f, 0.f);
    int e = start;
    for (; e + 4 <= end; e += 4) {
        int s0 = __ldg(g_srcs + e);
        int s1 = __ldg(g_srcs + e + 1);
        int s2 = __ldg(g_srcs + e + 2);
        int s3 = __ldg(g_srcs + e + 3);
        float2 v0 = __ldg(x2 + (size_t)s0 * 32 + l);
        float2 v1 = __ldg(x2 + (size_t)s1 * 32 + l);
        float2 v2 = __ldg(x2 + (size_t)s2 * 32 + l);
        float2 v3 = __ldg(x2 + (size_t)s3 * 32 + l);
        acc.x += v0.x + v1.x + v2.x + v3.x;
        acc.y += v0.y + v1.y + v2.y + v3.y;
    }
    for (; e < end; e++) {
        int s0 = __ldg(g_srcs + e);
        float2 v0 = __ldg(x2 + (size_t)s0 * 32 + l);
        acc.x += v0.x;
        acc.y += v0.y;
    }
    ((float2*)g_h)[(size_t)wid * 32 + l] = acc;
    if (l == 0) g_deg[wid] = (float)(end - start);
}

// ---------------------------------------------------------------------------
// 7) out = normalize( h @ Wm + x @ Ws + deg*bm + bs )  — proven R1 version
// ---------------------------------------------------------------------------
#define IN_STRIDE 132   // 128 + 4 pad

__global__ void k_transform(const float* __restrict__ x, float* __restrict__ out) {
    extern __shared__ float smem[];
    float* In  = smem;                    // [64][IN_STRIDE]
    float* Wsh = In + 64 * IN_STRIDE;     // [128][64] flat
    float* red = Wsh + 128 * D;           // [64][17]
    float* nf  = red + 64 * 17;           // [64]

    int tid = threadIdx.x;
    int n0  = blockIdx.x * 64;

    {
        const float4* wm4 = (const float4*)g_Wm;
        const float4* ws4 = (const float4*)g_Ws;
        float4* w4 = (float4*)Wsh;
        for (int i = tid; i < (D * D) / 4; i += 256) {
            w4[i] = wm4[i];
            w4[i + (D * D) / 4] = ws4[i];
        }
    }
    {
        const float4* h4 = (const float4*)g_h;
        const float4* x4 = (const float4*)x;
        for (int i = tid; i < 64 * (D / 4); i += 256) {
            int n = i >> 4, j = i & 15;
            int gn = n0 + n;
            float4 hv = make_float4(0.f, 0.f, 0.f, 0.f);
            float4 xv = hv;
            if (gn < NN) {
                size_t off = (size_t)gn * (D / 4) + j;
                hv = h4[off];
                xv = x4[off];
            }
            *(float4*)&In[n * IN_STRIDE + j * 4]      = hv;
            *(float4*)&In[n * IN_STRIDE + 64 + j * 4] = xv;
        }
    }
    __syncthreads();

    int to = tid & 15;
    int tn = tid >> 4;

    float acc[4][4];
    #pragma unroll
    for (int r = 0; r < 4; r++)
        #pragma unroll
        for (int c = 0; c < 4; c++) acc[r][c] = 0.f;

    const float* a0 = &In[(tn * 4 + 0) * IN_STRIDE];
    const float* a1 = &In[(tn * 4 + 1) * IN_STRIDE];
    const float* a2 = &In[(tn * 4 + 2) * IN_STRIDE];
    const float* a3 = &In[(tn * 4 + 3) * IN_STRIDE];

    #pragma unroll 8
    for (int k = 0; k < 128; k++) {
        float4 b = *(const float4*)&Wsh[k * D + to * 4];
        float v0 = a0[k], v1 = a1[k], v2 = a2[k], v3 = a3[k];
        acc[0][0] = fmaf(v0, b.x, acc[0][0]); acc[0][1] = fmaf(v0, b.y, acc[0][1]);
        acc[0][2] = fmaf(v0, b.z, acc[0][2]); acc[0][3] = fmaf(v0, b.w, acc[0][3]);
        acc[1][0] = fmaf(v1, b.x, acc[1][0]); acc[1][1] = fmaf(v1, b.y, acc[1][1]);
        acc[1][2] = fmaf(v1, b.z, acc[1][2]); acc[1][3] = fmaf(v1, b.w, acc[1][3]);
        acc[2][0] = fmaf(v2, b.x, acc[2][0]); acc[2][1] = fmaf(v2, b.y, acc[2][1]);
        acc[2][2] = fmaf(v2, b.z, acc[2][2]); acc[2][3] = fmaf(v2, b.w, acc[2][3]);
        acc[3][0] = fmaf(v3, b.x, acc[3][0]); acc[3][1] = fmaf(v3, b.y, acc[3][1]);
        acc[3][2] = fmaf(v3, b.z, acc[3][2]); acc[3][3] = fmaf(v3, b.w, acc[3][3]);
    }

    float bmv[4], bsv[4];
    #pragma unroll
    for (int c = 0; c < 4; c++) {
        bmv[c] = g_bm[to * 4 + c];
        bsv[c] = g_bs[to * 4 + c];
    }

    float vals[4][4];
    #pragma unroll
    for (int r = 0; r < 4; r++) {
        int gn = n0 + tn * 4 + r;
        float dg = (gn < NN) ? g_deg[gn] : 0.f;
        float ss = 0.f;
        #pragma unroll
        for (int c = 0; c < 4; c++) {
            float v = acc[r][c] + dg * bmv[c] + bsv[c];
            vals[r][c] = v;
            ss = fmaf(v, v, ss);
        }
        red[(tn * 4 + r) * 17 + to] = ss;
    }
    __syncthreads();

    if (tid < 64) {
        float s = 0.f;
        #pragma unroll
        for (int t2 = 0; t2 < 16; t2++) s += red[tid * 17 + t2];
        float nrm = sqrtf(s);
        nf[tid] = 1.f / fmaxf(nrm, 1e-12f);
    }
    __syncthreads();

    #pragma unroll
    for (int r = 0; r < 4; r++) {
        int gn = n0 + tn * 4 + r;
        if (gn < NN) {
            float f = nf[tn * 4 + r];
            float4 o4 = make_float4(vals[r][0] * f, vals[r][1] * f,
                                    vals[r][2] * f, vals[r][3] * f);
            *(float4*)&out[(size_t)gn * D + to * 4] = o4;
        }
    }
}

#define SMEM_BYTES ((64 * IN_STRIDE + 128 * D + 64 * 17 + 64) * (int)sizeof(float))

extern "C" void kernel_launch(void* const* d_in, const int* in_sizes, int n_in,
                              void* d_out, int out_size) {
    const float* x   = (const float*)d_in[0];
    const int*   ei  = (const int*)d_in[1];
    const float* bmw = (const float*)d_in[2];
    const float* bmb = (const float*)d_in[3];
    const float* bsw = (const float*)d_in[4];
    const float* bsb = (const float*)d_in[5];
    const float* lc  = (const float*)d_in[6];
    float* out = (float*)d_out;

    unsigned ehblk = (NE + 255u) / 256u;
    k_hist<<<ehblk + 1, 256>>>(ei, bmw, bmb, bsw, bsb, lc);
    k_scan1<<<NBLK_SCAN, 256>>>();
    k_scan2<<<1, 512>>>();
    k_scan3<<<NBLK_SCAN, 256>>>();
    k_fill<<<ehblk, 256>>>(ei);
    k_agg<<<(NN * 32 + 255) / 256, 256>>>((const float2*)x);

    cudaFuncSetAttribute(k_transform, cudaFuncAttributeMaxDynamicSharedMemorySize, SMEM_BYTES);
    k_transform<<<(NN + 63) / 64, 256, SMEM_BYTES>>>(x, out);
}